// round 1
// baseline (speedup 1.0000x reference)
#include <cuda_runtime.h>
#include <math.h>

#define H_DIM 768
#define D_DIM 384
#define L_DIM 128
#define B_MAX 32768

// scratch (no allocations allowed)
__device__ float g_x2[B_MAX];
__device__ float g_y2[L_DIM];

// ---------------------------------------------------------------------------
// Kernel 1: projected = cls @ W + b   (M=B, N=384, K=768)
// classic 128x128x8 SGEMM, 256 threads, 8x8 micro-tile
// writes projected into P (the x-region of d_out, used as scratch)
// ---------------------------------------------------------------------------
__global__ __launch_bounds__(256, 2)
void gemm_proj(const float* __restrict__ A, const float* __restrict__ Wm,
               const float* __restrict__ bias, float* __restrict__ P)
{
    __shared__ float As[8][128];
    __shared__ float Bs[8][128];

    const int tid = threadIdx.x;
    const int rowBase = blockIdx.y * 128;
    const int colBase = blockIdx.x * 128;
    const int tx = tid & 15;        // 0..15 -> col group
    const int ty = tid >> 4;        // 0..15 -> row group

    // A-tile load: 128 rows x 8 k; float4 along k
    const int arow = tid >> 1;           // 0..127
    const int acol = (tid & 1) << 2;     // 0 or 4
    // B-tile load: 8 k x 128 cols; float4 along n
    const int brow = tid >> 5;           // 0..7
    const int bcol = (tid & 31) << 2;    // 0..124

    float acc[8][8];
#pragma unroll
    for (int i = 0; i < 8; i++)
#pragma unroll
        for (int j = 0; j < 8; j++) acc[i][j] = 0.f;

    for (int kt = 0; kt < H_DIM; kt += 8) {
        float4 av = *(const float4*)(A + (size_t)(rowBase + arow) * H_DIM + kt + acol);
        As[acol + 0][arow] = av.x;
        As[acol + 1][arow] = av.y;
        As[acol + 2][arow] = av.z;
        As[acol + 3][arow] = av.w;
        float4 bv = *(const float4*)(Wm + (size_t)(kt + brow) * D_DIM + colBase + bcol);
        *(float4*)&Bs[brow][bcol] = bv;
        __syncthreads();

#pragma unroll
        for (int k = 0; k < 8; k++) {
            float a[8], b[8];
#pragma unroll
            for (int i = 0; i < 8; i++) a[i] = As[k][ty * 8 + i];
#pragma unroll
            for (int j = 0; j < 8; j++) b[j] = Bs[k][tx * 8 + j];
#pragma unroll
            for (int i = 0; i < 8; i++)
#pragma unroll
                for (int j = 0; j < 8; j++) acc[i][j] = fmaf(a[i], b[j], acc[i][j]);
        }
        __syncthreads();
    }

#pragma unroll
    for (int i = 0; i < 8; i++) {
        int r = rowBase + ty * 8 + i;
#pragma unroll
        for (int j = 0; j < 8; j++) {
            int c = colBase + tx * 8 + j;
            P[(size_t)r * D_DIM + c] = acc[i][j] + bias[c];
        }
    }
}

// ---------------------------------------------------------------------------
// Kernel 2: per-row expmap0 in place: x = tanh(||p||) * p / max(||p||,eps)
// also writes ||x||^2 to g_x2.  One block (128 threads) per row.
// ---------------------------------------------------------------------------
__global__ void expmap_rows(float* __restrict__ P)
{
    const int row = blockIdx.x;
    const int tid = threadIdx.x;       // 0..127
    float* p = P + (size_t)row * D_DIM;

    float v0 = p[tid];
    float v1 = p[tid + 128];
    float v2 = p[tid + 256];
    float s = v0 * v0 + v1 * v1 + v2 * v2;

    __shared__ float red[128];
    red[tid] = s;
    __syncthreads();
#pragma unroll
    for (int o = 64; o > 0; o >>= 1) {
        if (tid < o) red[tid] += red[tid + o];
        __syncthreads();
    }

    __shared__ float sh_scale;
    if (tid == 0) {
        float nsq = red[0];
        float n = sqrtf(nsq);
        n = fmaxf(n, 1e-15f);
        float t = tanhf(n);
        float scale = t / n;
        sh_scale = scale;
        g_x2[row] = nsq * scale * scale;   // ||x||^2
    }
    __syncthreads();

    float scale = sh_scale;
    p[tid]       = v0 * scale;
    p[tid + 128] = v1 * scale;
    p[tid + 256] = v2 * scale;
}

// ---------------------------------------------------------------------------
// Kernel 3: y2[j] = ||y_j||^2   (tiny)
// ---------------------------------------------------------------------------
__global__ void compute_y2(const float* __restrict__ Y)
{
    const int j = threadIdx.x;   // 128 threads
    const float* y = Y + (size_t)j * D_DIM;
    float s = 0.f;
#pragma unroll 4
    for (int d = 0; d < D_DIM; d++) s = fmaf(y[d], y[d], s);
    g_y2[j] = s;
}

// ---------------------------------------------------------------------------
// Kernel 4: logits = -2*atanh(sqrt(clip((x2+y2-2xy)/(1-2xy+x2*y2))))
// GEMM x[B,384] @ Y^T[384,128], 128x128x8 tiles (single column tile since L=128)
// ---------------------------------------------------------------------------
__global__ __launch_bounds__(256, 2)
void gemm_dist(const float* __restrict__ X, const float* __restrict__ Y,
               float* __restrict__ logits)
{
    __shared__ float As[8][128];
    __shared__ float Bs[8][128];

    const int tid = threadIdx.x;
    const int rowBase = blockIdx.y * 128;
    const int tx = tid & 15;
    const int ty = tid >> 4;

    const int arow = tid >> 1;
    const int acol = (tid & 1) << 2;

    float acc[8][8];
#pragma unroll
    for (int i = 0; i < 8; i++)
#pragma unroll
        for (int j = 0; j < 8; j++) acc[i][j] = 0.f;

    for (int kt = 0; kt < D_DIM; kt += 8) {
        float4 av = *(const float4*)(X + (size_t)(rowBase + arow) * D_DIM + kt + acol);
        As[acol + 0][arow] = av.x;
        As[acol + 1][arow] = av.y;
        As[acol + 2][arow] = av.z;
        As[acol + 3][arow] = av.w;
        // Y is [L, D] row-major; we need Bs[k][c] = Y[c, kt+k]
        float4 yv = *(const float4*)(Y + (size_t)arow * D_DIM + kt + acol);
        Bs[acol + 0][arow] = yv.x;
        Bs[acol + 1][arow] = yv.y;
        Bs[acol + 2][arow] = yv.z;
        Bs[acol + 3][arow] = yv.w;
        __syncthreads();

#pragma unroll
        for (int k = 0; k < 8; k++) {
            float a[8], b[8];
#pragma unroll
            for (int i = 0; i < 8; i++) a[i] = As[k][ty * 8 + i];
#pragma unroll
            for (int j = 0; j < 8; j++) b[j] = Bs[k][tx * 8 + j];
#pragma unroll
            for (int i = 0; i < 8; i++)
#pragma unroll
                for (int j = 0; j < 8; j++) acc[i][j] = fmaf(a[i], b[j], acc[i][j]);
        }
        __syncthreads();
    }

    const float CLIPMAX = (1.0f - 1e-5f) * (1.0f - 1e-5f);
#pragma unroll
    for (int i = 0; i < 8; i++) {
        int r = rowBase + ty * 8 + i;
        float x2 = g_x2[r];
#pragma unroll
        for (int j = 0; j < 8; j++) {
            int c = tx * 8 + j;
            float y2 = g_y2[c];
            float xy = acc[i][j];
            float sq = x2 + y2 - 2.0f * xy;
            float den = 1.0f - 2.0f * xy + x2 * y2;
            float ratio = sq / den;
            ratio = fminf(fmaxf(ratio, 0.0f), CLIPMAX);
            float dist = 2.0f * atanhf(sqrtf(ratio));
            logits[(size_t)r * L_DIM + c] = -dist;
        }
    }
}

// ---------------------------------------------------------------------------
extern "C" void kernel_launch(void* const* d_in, const int* in_sizes, int n_in,
                              void* d_out, int out_size)
{
    const float* cls  = (const float*)d_in[0];   // [B, 768]
    const float* Wm   = (const float*)d_in[1];   // [768, 384]
    const float* bias = (const float*)d_in[2];   // [384]
    const float* Y    = (const float*)d_in[3];   // [128, 384]

    const int B = in_sizes[0] / H_DIM;           // 32768

    float* out = (float*)d_out;
    float* logits = out;                          // [B, 128]
    float* x = out + (size_t)B * L_DIM;           // [B, 384]

    dim3 g1(D_DIM / 128, B / 128);
    gemm_proj<<<g1, 256>>>(cls, Wm, bias, x);

    expmap_rows<<<B, 128>>>(x);

    compute_y2<<<1, 128>>>(Y);

    dim3 g3(1, B / 128);
    gemm_dist<<<g3, 256>>>(x, Y, logits);
}

// round 3
// speedup vs baseline: 3.0370x; 3.0370x over previous
#include <cuda_runtime.h>
#include <math.h>
#include <cstdint>

#define H_DIM 768
#define D_DIM 384
#define L_DIM 128
#define B_MAX 32768

// -------- scratch (no runtime allocation allowed) --------
__device__ float g_x2[B_MAX];
__device__ float g_y2[L_DIM];
__device__ float g_Wt[(size_t)D_DIM * H_DIM];   // W transposed: [D, H]

// ---------------- helpers ----------------
__device__ __forceinline__ uint32_t smem_u32(const void* p) {
    uint32_t a;
    asm("{ .reg .u64 t; cvta.to.shared.u64 t, %1; cvt.u32.u64 %0, t; }" : "=r"(a) : "l"(p));
    return a;
}
__device__ __forceinline__ void cp_async16(uint32_t s, const void* g) {
    asm volatile("cp.async.cg.shared.global [%0], [%1], 16;" :: "r"(s), "l"(g));
}
#define CP_COMMIT asm volatile("cp.async.commit_group;" ::: "memory")
#define CP_WAIT1  asm volatile("cp.async.wait_group 1;" ::: "memory")
#define CP_WAIT0  asm volatile("cp.async.wait_group 0;" ::: "memory")

__device__ __forceinline__ void mma_tf32(float* d, const uint32_t* a, const uint32_t* b) {
    asm volatile(
        "mma.sync.aligned.m16n8k8.row.col.f32.tf32.tf32.f32 "
        "{%0,%1,%2,%3}, {%4,%5,%6,%7}, {%8,%9}, {%0,%1,%2,%3};"
        : "+f"(d[0]), "+f"(d[1]), "+f"(d[2]), "+f"(d[3])
        : "r"(a[0]), "r"(a[1]), "r"(a[2]), "r"(a[3]), "r"(b[0]), "r"(b[1]));
}

#define ASTR 36                       // 32 k-floats + 4 pad (bank-conflict-free)
#define STAGE_FLOATS (2 * 128 * ASTR) // A tile then B tile
#define STAGE_BYTES  (STAGE_FLOATS * 4)
#define SMEM_TOTAL   (2 * STAGE_BYTES)

// issue cp.async for one 128x32 A tile + 128x32 B tile (both [mn][k] stride ASTR)
__device__ __forceinline__ void stage_loads(uint32_t sstage, const float* Ag,
                                            const float* Bg, int ldA, int ldB, int tid) {
#pragma unroll
    for (int i = 0; i < 4; ++i) {
        int idx = i * 256 + tid;
        int row = idx >> 3, k4 = idx & 7;
        cp_async16(sstage + (uint32_t)((row * ASTR + k4 * 4) * 4),
                   Ag + (size_t)row * ldA + k4 * 4);
        cp_async16(sstage + (uint32_t)((128 * ASTR + row * ASTR + k4 * 4) * 4),
                   Bg + (size_t)row * ldB + k4 * 4);
    }
}

// load frags + 16 mmas for one k8 step
__device__ __forceinline__ void compute_k8(const float* As, const float* Bs,
                                           int kb, int wm, int wn, int lane,
                                           float acc[4][4][4]) {
    uint32_t af[4][4];
#pragma unroll
    for (int mt = 0; mt < 4; ++mt) {
        int r = wm + mt * 16 + (lane >> 2);
        int cc = kb + (lane & 3);
        af[mt][0] = __float_as_uint(As[r * ASTR + cc]);
        af[mt][1] = __float_as_uint(As[(r + 8) * ASTR + cc]);
        af[mt][2] = __float_as_uint(As[r * ASTR + cc + 4]);
        af[mt][3] = __float_as_uint(As[(r + 8) * ASTR + cc + 4]);
    }
    uint32_t bf[4][2];
#pragma unroll
    for (int nt = 0; nt < 4; ++nt) {
        int n = wn + nt * 8 + (lane >> 2);
        bf[nt][0] = __float_as_uint(Bs[n * ASTR + kb + (lane & 3)]);
        bf[nt][1] = __float_as_uint(Bs[n * ASTR + kb + 4 + (lane & 3)]);
    }
#pragma unroll
    for (int mt = 0; mt < 4; ++mt)
#pragma unroll
        for (int nt = 0; nt < 4; ++nt)
            mma_tf32(acc[mt][nt], af[mt], bf[nt]);
}

// ---------------- small kernels ----------------
__global__ void transpose_w(const float* __restrict__ W) {
    __shared__ float t[32][33];
    int bx = blockIdx.x * 32;  // H dim
    int by = blockIdx.y * 32;  // D dim
    int x = threadIdx.x, y = threadIdx.y;   // 32 x 8
#pragma unroll
    for (int i = 0; i < 32; i += 8)
        t[y + i][x] = W[(size_t)(bx + y + i) * D_DIM + by + x];
    __syncthreads();
#pragma unroll
    for (int i = 0; i < 32; i += 8)
        g_Wt[(size_t)(by + y + i) * H_DIM + bx + x] = t[x][y + i];
}

__global__ void compute_y2(const float* __restrict__ Y) {
    const int j = threadIdx.x;
    const float* y = Y + (size_t)j * D_DIM;
    float s = 0.f;
#pragma unroll 4
    for (int d = 0; d < D_DIM; d++) s = fmaf(y[d], y[d], s);
    g_y2[j] = s;
}

// expmap0 in place + x2
__global__ void expmap_rows(float* __restrict__ P) {
    const int row = blockIdx.x;
    const int tid = threadIdx.x;       // 128
    float* p = P + (size_t)row * D_DIM;

    float v0 = p[tid];
    float v1 = p[tid + 128];
    float v2 = p[tid + 256];
    float s = v0 * v0 + v1 * v1 + v2 * v2;

    __shared__ float red[128];
    red[tid] = s;
    __syncthreads();
#pragma unroll
    for (int o = 64; o > 0; o >>= 1) {
        if (tid < o) red[tid] += red[tid + o];
        __syncthreads();
    }
    __shared__ float sh_scale;
    if (tid == 0) {
        float nsq = red[0];
        float n = fmaxf(sqrtf(nsq), 1e-15f);
        float t = tanhf(n);
        float scale = t / n;
        sh_scale = scale;
        g_x2[row] = nsq * scale * scale;
    }
    __syncthreads();
    float scale = sh_scale;
    p[tid]       = v0 * scale;
    p[tid + 128] = v1 * scale;
    p[tid + 256] = v2 * scale;
}

// ---------------- GEMM1: projected = cls @ W + b ----------------
__global__ __launch_bounds__(256, 2)
void gemm1_mma(const float* __restrict__ A, const float* __restrict__ bias,
               float* __restrict__ P)
{
    extern __shared__ float sm[];
    const uint32_t sb = smem_u32(sm);
    const int tid = threadIdx.x, lane = tid & 31, warp = tid >> 5;
    const int wm = (warp >> 2) * 64, wn = (warp & 3) * 32;
    const int rowBase = blockIdx.y * 128, colBase = blockIdx.x * 128;

    const float* Abase = A + (size_t)rowBase * H_DIM;
    const float* Bbase = g_Wt + (size_t)colBase * H_DIM;

    float acc[4][4][4];
#pragma unroll
    for (int mt = 0; mt < 4; ++mt)
#pragma unroll
        for (int nt = 0; nt < 4; ++nt)
#pragma unroll
            for (int q = 0; q < 4; ++q) acc[mt][nt][q] = 0.f;

    stage_loads(sb, Abase, Bbase, H_DIM, H_DIM, tid);
    CP_COMMIT;

    const int NCH = H_DIM / 32;   // 24
    for (int c = 0; c < NCH; ++c) {
        const int buf = c & 1;
        if (c + 1 < NCH) {
            stage_loads(sb + (buf ^ 1) * STAGE_BYTES,
                        Abase + (c + 1) * 32, Bbase + (c + 1) * 32, H_DIM, H_DIM, tid);
            CP_COMMIT;
            CP_WAIT1;
        } else {
            CP_WAIT0;
        }
        __syncthreads();
        const float* As = sm + buf * STAGE_FLOATS;
        const float* Bs = As + 128 * ASTR;
#pragma unroll
        for (int ks = 0; ks < 4; ++ks)
            compute_k8(As, Bs, ks * 8, wm, wn, lane, acc);
        __syncthreads();
    }

#pragma unroll
    for (int mt = 0; mt < 4; ++mt) {
        int r0 = rowBase + wm + mt * 16 + (lane >> 2);
#pragma unroll
        for (int nt = 0; nt < 4; ++nt) {
            int cc = colBase + wn + nt * 8 + (lane & 3) * 2;
            float b0 = bias[cc], b1 = bias[cc + 1];
            float2 v0 = make_float2(acc[mt][nt][0] + b0, acc[mt][nt][1] + b1);
            float2 v1 = make_float2(acc[mt][nt][2] + b0, acc[mt][nt][3] + b1);
            *(float2*)&P[(size_t)r0 * D_DIM + cc] = v0;
            *(float2*)&P[(size_t)(r0 + 8) * D_DIM + cc] = v1;
        }
    }
}

// ---------------- GEMM2: xy = x @ Y^T, fused Poincare distance ----------------
__global__ __launch_bounds__(256, 2)
void gemm2_mma(const float* __restrict__ X, const float* __restrict__ Y,
               float* __restrict__ logits)
{
    extern __shared__ float sm[];
    const uint32_t sb = smem_u32(sm);
    const int tid = threadIdx.x, lane = tid & 31, warp = tid >> 5;
    const int wm = (warp >> 2) * 64, wn = (warp & 3) * 32;
    const int rowBase = blockIdx.x * 128;

    const float* Abase = X + (size_t)rowBase * D_DIM;
    const float* Bbase = Y;   // [128, 384] already n-major/k-contig

    float acc[4][4][4];
#pragma unroll
    for (int mt = 0; mt < 4; ++mt)
#pragma unroll
        for (int nt = 0; nt < 4; ++nt)
#pragma unroll
            for (int q = 0; q < 4; ++q) acc[mt][nt][q] = 0.f;

    stage_loads(sb, Abase, Bbase, D_DIM, D_DIM, tid);
    CP_COMMIT;

    const int NCH = D_DIM / 32;   // 12
    for (int c = 0; c < NCH; ++c) {
        const int buf = c & 1;
        if (c + 1 < NCH) {
            stage_loads(sb + (buf ^ 1) * STAGE_BYTES,
                        Abase + (c + 1) * 32, Bbase + (c + 1) * 32, D_DIM, D_DIM, tid);
            CP_COMMIT;
            CP_WAIT1;
        } else {
            CP_WAIT0;
        }
        __syncthreads();
        const float* As = sm + buf * STAGE_FLOATS;
        const float* Bs = As + 128 * ASTR;
#pragma unroll
        for (int ks = 0; ks < 4; ++ks)
            compute_k8(As, Bs, ks * 8, wm, wn, lane, acc);
        __syncthreads();
    }

    const float CLIPMAX = (1.0f - 1e-5f) * (1.0f - 1e-5f);
#pragma unroll
    for (int mt = 0; mt < 4; ++mt) {
        int r0 = rowBase + wm + mt * 16 + (lane >> 2);
        float x2a = g_x2[r0];
        float x2b = g_x2[r0 + 8];
#pragma unroll
        for (int nt = 0; nt < 4; ++nt) {
            int cc = wn + nt * 8 + (lane & 3) * 2;
            float y2a = g_y2[cc], y2b = g_y2[cc + 1];
            float o[4];
#pragma unroll
            for (int q = 0; q < 4; ++q) {
                float xy = acc[mt][nt][q];
                float x2 = (q < 2) ? x2a : x2b;
                float y2 = (q & 1) ? y2b : y2a;
                float sq  = x2 + y2 - 2.0f * xy;
                float den = 1.0f - 2.0f * xy + x2 * y2;
                float ratio = sq / den;
                ratio = fminf(fmaxf(ratio, 0.0f), CLIPMAX);
                o[q] = -2.0f * atanhf(sqrtf(ratio));
            }
            *(float2*)&logits[(size_t)r0 * L_DIM + cc]       = make_float2(o[0], o[1]);
            *(float2*)&logits[(size_t)(r0 + 8) * L_DIM + cc] = make_float2(o[2], o[3]);
        }
    }
}

// ---------------------------------------------------------------------------
extern "C" void kernel_launch(void* const* d_in, const int* in_sizes, int n_in,
                              void* d_out, int out_size)
{
    const float* cls  = (const float*)d_in[0];   // [B, 768]
    const float* Wm   = (const float*)d_in[1];   // [768, 384]
    const float* bias = (const float*)d_in[2];   // [384]
    const float* Y    = (const float*)d_in[3];   // [128, 384]

    const int B = in_sizes[0] / H_DIM;

    float* out = (float*)d_out;
    float* logits = out;                          // [B, 128]
    float* x = out + (size_t)B * L_DIM;           // [B, 384]

    static bool attr_set = false;
    if (!attr_set) {
        cudaFuncSetAttribute(gemm1_mma, cudaFuncAttributeMaxDynamicSharedMemorySize, SMEM_TOTAL);
        cudaFuncSetAttribute(gemm2_mma, cudaFuncAttributeMaxDynamicSharedMemorySize, SMEM_TOTAL);
        attr_set = true;
    }

    transpose_w<<<dim3(H_DIM / 32, D_DIM / 32), dim3(32, 8)>>>(Wm);
    compute_y2<<<1, 128>>>(Y);
    gemm1_mma<<<dim3(D_DIM / 128, B / 128), 256, SMEM_TOTAL>>>(cls, bias, x);
    expmap_rows<<<B, 128>>>(x);
    gemm2_mma<<<B / 128, 256, SMEM_TOTAL>>>(x, Y, logits);
}